// round 5
// baseline (speedup 1.0000x reference)
#include <cuda_runtime.h>
#include <cuda_bf16.h>
#include <cstdint>

// ActuatorNet via warp-level mma.sync (HMMA) with bf16 hi/lo split (3 terms).
// Round 5 changes vs round 4:
//  - fragment table moved smem -> __device__ global (built by init kernel,
//    read via __ldg, L1-resident). smem drops 81KB -> ~6KB.
//  - __launch_bounds__(256,3): 3 CTAs/SM = 24 warps (was 14).
//  - pairwise-reciprocal softsign: 8 MUFU/layer instead of 16.
//  - bias pre-duplicated as float4 in fragment order (LDS.128, no dup MOVs).
//  - act[] fused into accumulator array (saves 16 regs).

#define NTHREADS 256
#define NWARPS   8

typedef unsigned long long u64;

__device__ u64 g_frag[19 * 16 * 32];   // [l][combo][lane], combo=term*8+ks*4+nb

// smem layout (bytes)
#define SM_W1     0                      // 192 f32 = 768
#define SM_B1     768                    // 32 f32 = 128
#define SM_BIAS4  896                    // 19*16 float4 = 4864
#define SM_WOUT   5760                   // 32 f32 = 128
#define SM_BOUT   5888                   // 1 f32
#define SM_TOTAL  5904

__device__ __forceinline__ uint32_t cvt_bf16x2(float hi_elem, float lo_elem) {
    uint32_t r;
    asm("cvt.rn.bf16x2.f32 %0, %1, %2;" : "=r"(r) : "f"(hi_elem), "f"(lo_elem));
    return r;
}

__device__ __forceinline__ float rcp_fast(float v) {
    float r;
    asm("rcp.approx.f32 %0, %1;" : "=f"(r) : "f"(v));
    return r;
}

__device__ __forceinline__ void mma_bf16(float* d,
                                         uint32_t a0, uint32_t a1,
                                         uint32_t a2, uint32_t a3,
                                         uint32_t b0, uint32_t b1) {
    asm volatile(
        "mma.sync.aligned.m16n8k16.row.col.f32.bf16.bf16.f32 "
        "{%0,%1,%2,%3}, {%4,%5,%6,%7}, {%8,%9}, {%0,%1,%2,%3};"
        : "+f"(d[0]), "+f"(d[1]), "+f"(d[2]), "+f"(d[3])
        : "r"(a0), "r"(a1), "r"(a2), "r"(a3), "r"(b0), "r"(b1));
}

// ---- init kernel: build per-thread B fragments (hi & lo) in global ----
__global__ void build_frag_kernel(const float* __restrict__ Wh) {
    int idx = blockIdx.x * 256 + threadIdx.x;
    if (idx >= 19 * 16 * 32) return;
    int lane  = idx & 31;
    int combo = (idx >> 5) & 15;
    int l     = idx >> 9;
    int nb    = combo & 3;
    int ks    = (combo >> 2) & 1;
    int term  = combo >> 3;            // 0 = hi, 1 = lo
    int col   = nb * 8 + (lane >> 2);
    int q     = lane & 3;
    int k0    = ks * 16 + q * 2;

    const float* Wl = Wh + l * 1024;
    float w0 = Wl[(k0 + 0) * 32 + col];
    float w1 = Wl[(k0 + 1) * 32 + col];
    float w2 = Wl[(k0 + 8) * 32 + col];
    float w3 = Wl[(k0 + 9) * 32 + col];

    uint32_t rb0, rb1;
    if (term == 0) {
        rb0 = cvt_bf16x2(w1, w0);
        rb1 = cvt_bf16x2(w3, w2);
    } else {
        float r0 = w0 - __bfloat162float(__float2bfloat16(w0));
        float r1 = w1 - __bfloat162float(__float2bfloat16(w1));
        float r2 = w2 - __bfloat162float(__float2bfloat16(w2));
        float r3 = w3 - __bfloat162float(__float2bfloat16(w3));
        rb0 = cvt_bf16x2(r1, r0);
        rb1 = cvt_bf16x2(r3, r2);
    }
    g_frag[idx] = ((u64)rb1 << 32) | rb0;
}

__global__ __launch_bounds__(NTHREADS, 3)
void actuator_hmma_kernel(const float* __restrict__ x,
                          const float* __restrict__ W1,
                          const float* __restrict__ b1,
                          const float* __restrict__ bh,
                          const float* __restrict__ Wout,
                          const float* __restrict__ bout,
                          float* __restrict__ out,
                          int B, int ntiles)
{
    extern __shared__ char smem[];
    float*  sW1   = (float*)(smem + SM_W1);
    float*  sB1   = (float*)(smem + SM_B1);
    float4* sB4   = (float4*)(smem + SM_BIAS4);
    float*  sWOUT = (float*)(smem + SM_WOUT);
    float*  sBOUT = (float*)(smem + SM_BOUT);

    const int tid = threadIdx.x;

    for (int i = tid; i < 192; i += NTHREADS) sW1[i] = W1[i];
    for (int i = tid; i < 32;  i += NTHREADS) sB1[i] = b1[i];
    for (int i = tid; i < 32;  i += NTHREADS) sWOUT[i] = Wout[i];
    if (tid == 0) sBOUT[0] = bout[0];
    // bias duplicated in D-fragment order: sB4[l*16 + nb*4 + q] = (bx,by,bx,by)
    for (int i = tid; i < 19 * 16; i += NTHREADS) {
        int l  = i >> 4;
        int nb = (i >> 2) & 3;
        int q  = i & 3;
        float bx = bh[l * 32 + nb * 8 + q * 2];
        float by = bh[l * 32 + nb * 8 + q * 2 + 1];
        sB4[i] = make_float4(bx, by, bx, by);
    }
    __syncthreads();

    const int wid  = tid >> 5;
    const int lane = tid & 31;
    const int g    = lane >> 2;
    const int q    = lane & 3;

    const float bias_out = sBOUT[0];

    for (int tile = blockIdx.x * NWARPS + wid; tile < ntiles;
         tile += gridDim.x * NWARPS) {

        int r0 = tile * 16 + g;
        int r1 = r0 + 8;
        int r0c = min(r0, B - 1);
        int r1c = min(r1, B - 1);

        // acc doubles as activation storage:
        // acc[nb*4+{0,1,2,3}] = h[r0][nb*8+2q], h[r0][nb*8+2q+1],
        //                       h[r1][nb*8+2q], h[r1][nb*8+2q+1]
        float acc[16];

        // ---- layer 1 (6 -> 32), fp32 SIMT ----
        {
            float xa[6], xb[6];
            const float* pa = x + (long long)r0c * 6;
            const float* pb = x + (long long)r1c * 6;
            #pragma unroll
            for (int i = 0; i < 6; i++) { xa[i] = __ldg(pa + i); xb[i] = __ldg(pb + i); }
            #pragma unroll
            for (int nb = 0; nb < 4; nb++) {
                int c0 = nb * 8 + q * 2;
                float s00 = sB1[c0], s01 = sB1[c0 + 1];
                float s10 = s00,     s11 = s01;
                #pragma unroll
                for (int i = 0; i < 6; i++) {
                    float w0 = sW1[i * 32 + c0], w1 = sW1[i * 32 + c0 + 1];
                    s00 += xa[i] * w0; s01 += xa[i] * w1;
                    s10 += xb[i] * w0; s11 += xb[i] * w1;
                }
                acc[nb * 4 + 0] = s00; acc[nb * 4 + 1] = s01;
                acc[nb * 4 + 2] = s10; acc[nb * 4 + 3] = s11;
            }
            // pairwise-reciprocal softsign
            #pragma unroll
            for (int p = 0; p < 8; p++) {
                float x0 = acc[2 * p], x1 = acc[2 * p + 1];
                float t0 = 1.0f + fabsf(x0);
                float t1 = 1.0f + fabsf(x1);
                float r = rcp_fast(t0 * t1);
                acc[2 * p]     = x0 * t1 * r;
                acc[2 * p + 1] = x1 * t0 * r;
            }
        }

        // ---- 19 hidden layers via HMMA ----
        for (int l = 0; l < 19; l++) {
            // B fragments from global (L1-resident table)
            const u64* fl = g_frag + l * 512 + lane;
            u64 Bhi[8], Blo[8];
            #pragma unroll
            for (int c = 0; c < 8; c++) Bhi[c] = __ldg(fl + c * 32);
            #pragma unroll
            for (int c = 0; c < 8; c++) Blo[c] = __ldg(fl + (8 + c) * 32);

            // split activations into bf16 hi/lo A fragments
            uint32_t ahi[8], alo[8];
            #pragma unroll
            for (int p = 0; p < 8; p++) {
                float e0 = acc[2 * p], e1 = acc[2 * p + 1];
                uint32_t hp = cvt_bf16x2(e1, e0);
                float f0 = __uint_as_float(hp << 16);
                float f1 = __uint_as_float(hp & 0xFFFF0000u);
                ahi[p] = hp;
                alo[p] = cvt_bf16x2(e1 - f1, e0 - f0);
            }

            // re-init accumulators from duplicated bias table
            const float4* b4 = sB4 + l * 16 + q;
            #pragma unroll
            for (int nb = 0; nb < 4; nb++) {
                float4 bb = b4[nb * 4];
                acc[nb * 4 + 0] = bb.x; acc[nb * 4 + 1] = bb.y;
                acc[nb * 4 + 2] = bb.z; acc[nb * 4 + 3] = bb.w;
            }

            #pragma unroll
            for (int ks = 0; ks < 2; ks++) {
                uint32_t a0 = ahi[ks*4+0], a1 = ahi[ks*4+1],
                         a2 = ahi[ks*4+2], a3 = ahi[ks*4+3];
                uint32_t l0 = alo[ks*4+0], l1 = alo[ks*4+1],
                         l2 = alo[ks*4+2], l3 = alo[ks*4+3];
                #pragma unroll
                for (int nb = 0; nb < 4; nb++) {
                    u64 wh = Bhi[ks*4+nb], wl = Blo[ks*4+nb];
                    uint32_t bh0 = (uint32_t)wh, bh1 = (uint32_t)(wh >> 32);
                    uint32_t bl0 = (uint32_t)wl, bl1 = (uint32_t)(wl >> 32);
                    float* d = acc + nb * 4;
                    mma_bf16(d, a0, a1, a2, a3, bh0, bh1);  // hi*Whi
                    mma_bf16(d, l0, l1, l2, l3, bh0, bh1);  // lo*Whi
                    mma_bf16(d, a0, a1, a2, a3, bl0, bl1);  // hi*Wlo
                }
            }

            // pairwise-reciprocal softsign, in place
            #pragma unroll
            for (int p = 0; p < 8; p++) {
                float x0 = acc[2 * p], x1 = acc[2 * p + 1];
                float t0 = 1.0f + fabsf(x0);
                float t1 = 1.0f + fabsf(x1);
                float r = rcp_fast(t0 * t1);
                acc[2 * p]     = x0 * t1 * r;
                acc[2 * p + 1] = x1 * t0 * r;
            }
        }

        // ---- output layer (32 -> 1) + quad reduction ----
        float po0 = 0.0f, po1 = 0.0f;
        #pragma unroll
        for (int nb = 0; nb < 4; nb++) {
            int c0 = nb * 8 + q * 2;
            float w0 = sWOUT[c0], w1 = sWOUT[c0 + 1];
            po0 += acc[nb * 4 + 0] * w0 + acc[nb * 4 + 1] * w1;
            po1 += acc[nb * 4 + 2] * w0 + acc[nb * 4 + 3] * w1;
        }
        po0 += __shfl_xor_sync(0xFFFFFFFFu, po0, 1);
        po0 += __shfl_xor_sync(0xFFFFFFFFu, po0, 2);
        po1 += __shfl_xor_sync(0xFFFFFFFFu, po1, 1);
        po1 += __shfl_xor_sync(0xFFFFFFFFu, po1, 2);
        if (q == 0) {
            if (r0 < B) out[r0] = po0 + bias_out;
            if (r1 < B) out[r1] = po1 + bias_out;
        }
    }
}

extern "C" void kernel_launch(void* const* d_in, const int* in_sizes, int n_in,
                              void* d_out, int out_size)
{
    const float* x    = (const float*)d_in[0];
    const float* W1   = (const float*)d_in[1];
    const float* b1   = (const float*)d_in[2];
    const float* Wh   = (const float*)d_in[3];
    const float* bh   = (const float*)d_in[4];
    const float* Wout = (const float*)d_in[5];
    const float* bout = (const float*)d_in[6];
    float* out = (float*)d_out;

    int B = in_sizes[0] / 6;
    int ntiles = (B + 15) / 16;

    build_frag_kernel<<<(19 * 16 * 32 + 255) / 256, 256>>>(Wh);

    int grid = 444;   // persistent: 3 CTAs/SM x 148 SMs
    actuator_hmma_kernel<<<grid, NTHREADS, SM_TOTAL>>>(
        x, W1, b1, bh, Wout, bout, out, B, ntiles);
}

// round 6
// speedup vs baseline: 1.0358x; 1.0358x over previous
#include <cuda_runtime.h>
#include <cuda_bf16.h>
#include <cstdint>

// ActuatorNet via warp-level mma.sync (HMMA, bf16 hi/lo 3-term split).
// Round 6 = round 4 (smem fragment table, LDS) + occupancy via 384-thread
// CTAs (2 CTAs/SM = 24 warps) + pairwise-reciprocal softsign + float4 bias.
// B fragments loaded per ks-step to shorten live ranges (fits 85 regs).

#define NTHREADS 384
#define NWARPS   12

typedef unsigned long long u64;

// smem layout (bytes)
#define SM_FRAG   0                      // 19*16*32 u64 = 77824
#define SM_W1     77824                  // 192 f32 = 768
#define SM_B1     (SM_W1 + 768)          // 32 f32 = 128
#define SM_BIAS4  (SM_B1 + 128)          // 19*16 float4 = 4864
#define SM_WOUT   (SM_BIAS4 + 4864)      // 32 f32 = 128
#define SM_BOUT   (SM_WOUT + 128)        // 1 f32
#define SM_TOTAL  (SM_BOUT + 16)         // 83744 B -> 2 CTAs/SM fits 228KB

__device__ __forceinline__ uint32_t cvt_bf16x2(float hi_elem, float lo_elem) {
    uint32_t r;
    asm("cvt.rn.bf16x2.f32 %0, %1, %2;" : "=r"(r) : "f"(hi_elem), "f"(lo_elem));
    return r;
}

__device__ __forceinline__ float rcp_fast(float v) {
    float r;
    asm("rcp.approx.f32 %0, %1;" : "=f"(r) : "f"(v));
    return r;
}

__device__ __forceinline__ void mma_bf16(float* d,
                                         uint32_t a0, uint32_t a1,
                                         uint32_t a2, uint32_t a3,
                                         uint32_t b0, uint32_t b1) {
    asm volatile(
        "mma.sync.aligned.m16n8k16.row.col.f32.bf16.bf16.f32 "
        "{%0,%1,%2,%3}, {%4,%5,%6,%7}, {%8,%9}, {%0,%1,%2,%3};"
        : "+f"(d[0]), "+f"(d[1]), "+f"(d[2]), "+f"(d[3])
        : "r"(a0), "r"(a1), "r"(a2), "r"(a3), "r"(b0), "r"(b1));
}

__global__ __launch_bounds__(NTHREADS, 2)
void actuator_hmma_kernel(const float* __restrict__ x,
                          const float* __restrict__ W1,
                          const float* __restrict__ b1,
                          const float* __restrict__ Wh,
                          const float* __restrict__ bh,
                          const float* __restrict__ Wout,
                          const float* __restrict__ bout,
                          float* __restrict__ out,
                          int B, int ntiles)
{
    extern __shared__ char smem[];
    u64*    sFRAG = (u64*)(smem + SM_FRAG);
    float*  sW1   = (float*)(smem + SM_W1);
    float*  sB1   = (float*)(smem + SM_B1);
    float4* sB4   = (float4*)(smem + SM_BIAS4);
    float*  sWOUT = (float*)(smem + SM_WOUT);
    float*  sBOUT = (float*)(smem + SM_BOUT);

    const int tid = threadIdx.x;

    // ---- stage small fp32 params ----
    for (int i = tid; i < 192; i += NTHREADS) sW1[i] = W1[i];
    for (int i = tid; i < 32;  i += NTHREADS) sB1[i] = b1[i];
    for (int i = tid; i < 32;  i += NTHREADS) sWOUT[i] = Wout[i];
    if (tid == 0) sBOUT[0] = bout[0];
    // bias duplicated in D-fragment order: sB4[l*16+nb*4+q]=(bx,by,bx,by)
    for (int i = tid; i < 19 * 16; i += NTHREADS) {
        int l  = i >> 4;
        int nb = (i >> 2) & 3;
        int qq = i & 3;
        float bx = bh[l * 32 + nb * 8 + qq * 2];
        float by = bh[l * 32 + nb * 8 + qq * 2 + 1];
        sB4[i] = make_float4(bx, by, bx, by);
    }

    // ---- stage hidden weights as per-thread B fragments (hi & lo) ----
    // slot = ((l*16 + combo)*32 + lane), combo = term*8 + ks*4 + nb
    for (int idx = tid; idx < 19 * 16 * 32; idx += NTHREADS) {
        int lane  = idx & 31;
        int combo = (idx >> 5) & 15;
        int l     = idx >> 9;
        int nb    = combo & 3;
        int ks    = (combo >> 2) & 1;
        int term  = combo >> 3;            // 0 = hi, 1 = lo
        int col   = nb * 8 + (lane >> 2);
        int qq    = lane & 3;
        int k0    = ks * 16 + qq * 2;

        const float* Wl = Wh + l * 1024;
        float w0 = Wl[(k0 + 0) * 32 + col];
        float w1 = Wl[(k0 + 1) * 32 + col];
        float w2 = Wl[(k0 + 8) * 32 + col];
        float w3 = Wl[(k0 + 9) * 32 + col];

        uint32_t rb0, rb1;
        if (term == 0) {
            rb0 = cvt_bf16x2(w1, w0);
            rb1 = cvt_bf16x2(w3, w2);
        } else {
            float r0 = w0 - __bfloat162float(__float2bfloat16(w0));
            float r1 = w1 - __bfloat162float(__float2bfloat16(w1));
            float r2 = w2 - __bfloat162float(__float2bfloat16(w2));
            float r3 = w3 - __bfloat162float(__float2bfloat16(w3));
            rb0 = cvt_bf16x2(r1, r0);
            rb1 = cvt_bf16x2(r3, r2);
        }
        sFRAG[idx] = ((u64)rb1 << 32) | rb0;
    }
    __syncthreads();

    const int wid  = tid >> 5;
    const int lane = tid & 31;
    const int g    = lane >> 2;
    const int q    = lane & 3;

    const float bias_out = sBOUT[0];

    for (int tile = blockIdx.x * NWARPS + wid; tile < ntiles;
         tile += gridDim.x * NWARPS) {

        int r0 = tile * 16 + g;
        int r1 = r0 + 8;
        int r0c = min(r0, B - 1);
        int r1c = min(r1, B - 1);

        // acc doubles as activation storage:
        // acc[nb*4+{0..3}] = h[r0][nb*8+2q], h[r0][nb*8+2q+1],
        //                    h[r1][nb*8+2q], h[r1][nb*8+2q+1]
        float acc[16];

        // ---- layer 1 (6 -> 32), fp32 SIMT ----
        {
            float xa[6], xb[6];
            const float* pa = x + (long long)r0c * 6;
            const float* pb = x + (long long)r1c * 6;
            #pragma unroll
            for (int i = 0; i < 6; i++) { xa[i] = __ldg(pa + i); xb[i] = __ldg(pb + i); }
            #pragma unroll
            for (int nb = 0; nb < 4; nb++) {
                int c0 = nb * 8 + q * 2;
                float s00 = sB1[c0], s01 = sB1[c0 + 1];
                float s10 = s00,     s11 = s01;
                #pragma unroll
                for (int i = 0; i < 6; i++) {
                    float w0 = sW1[i * 32 + c0], w1 = sW1[i * 32 + c0 + 1];
                    s00 += xa[i] * w0; s01 += xa[i] * w1;
                    s10 += xb[i] * w0; s11 += xb[i] * w1;
                }
                acc[nb * 4 + 0] = s00; acc[nb * 4 + 1] = s01;
                acc[nb * 4 + 2] = s10; acc[nb * 4 + 3] = s11;
            }
            #pragma unroll
            for (int p = 0; p < 8; p++) {
                float x0 = acc[2 * p], x1 = acc[2 * p + 1];
                float t0 = 1.0f + fabsf(x0);
                float t1 = 1.0f + fabsf(x1);
                float r = rcp_fast(t0 * t1);
                acc[2 * p]     = x0 * t1 * r;
                acc[2 * p + 1] = x1 * t0 * r;
            }
        }

        // ---- 19 hidden layers via HMMA ----
        for (int l = 0; l < 19; l++) {
            // split activations into bf16 hi/lo A fragments
            uint32_t ahi[8], alo[8];
            #pragma unroll
            for (int p = 0; p < 8; p++) {
                float e0 = acc[2 * p], e1 = acc[2 * p + 1];
                uint32_t hp = cvt_bf16x2(e1, e0);
                float f0 = __uint_as_float(hp << 16);
                float f1 = __uint_as_float(hp & 0xFFFF0000u);
                ahi[p] = hp;
                alo[p] = cvt_bf16x2(e1 - f1, e0 - f0);
            }

            // re-init accumulators from duplicated bias table
            const float4* b4 = sB4 + l * 16 + q;
            #pragma unroll
            for (int nb = 0; nb < 4; nb++) {
                float4 bb = b4[nb * 4];
                acc[nb * 4 + 0] = bb.x; acc[nb * 4 + 1] = bb.y;
                acc[nb * 4 + 2] = bb.z; acc[nb * 4 + 3] = bb.w;
            }

            // per ks-step: load 4 hi + 4 lo B fragments, then 12 MMA
            const u64* fl = sFRAG + l * 512 + lane;
            #pragma unroll
            for (int ks = 0; ks < 2; ks++) {
                u64 Bhi[4], Blo[4];
                #pragma unroll
                for (int nb = 0; nb < 4; nb++) {
                    Bhi[nb] = fl[(ks * 4 + nb) * 32];
                    Blo[nb] = fl[(8 + ks * 4 + nb) * 32];
                }
                uint32_t a0 = ahi[ks*4+0], a1 = ahi[ks*4+1],
                         a2 = ahi[ks*4+2], a3 = ahi[ks*4+3];
                uint32_t l0 = alo[ks*4+0], l1 = alo[ks*4+1],
                         l2 = alo[ks*4+2], l3 = alo[ks*4+3];
                #pragma unroll
                for (int nb = 0; nb < 4; nb++) {
                    uint32_t bh0 = (uint32_t)Bhi[nb], bh1 = (uint32_t)(Bhi[nb] >> 32);
                    uint32_t bl0 = (uint32_t)Blo[nb], bl1 = (uint32_t)(Blo[nb] >> 32);
                    float* d = acc + nb * 4;
                    mma_bf16(d, a0, a1, a2, a3, bh0, bh1);  // hi*Whi
                    mma_bf16(d, l0, l1, l2, l3, bh0, bh1);  // lo*Whi
                    mma_bf16(d, a0, a1, a2, a3, bl0, bl1);  // hi*Wlo
                }
            }

            // pairwise-reciprocal softsign, in place
            #pragma unroll
            for (int p = 0; p < 8; p++) {
                float x0 = acc[2 * p], x1 = acc[2 * p + 1];
                float t0 = 1.0f + fabsf(x0);
                float t1 = 1.0f + fabsf(x1);
                float r = rcp_fast(t0 * t1);
                acc[2 * p]     = x0 * t1 * r;
                acc[2 * p + 1] = x1 * t0 * r;
            }
        }

        // ---- output layer (32 -> 1) + quad reduction ----
        float po0 = 0.0f, po1 = 0.0f;
        #pragma unroll
        for (int nb = 0; nb < 4; nb++) {
            int c0 = nb * 8 + q * 2;
            float w0 = sWOUT[c0], w1 = sWOUT[c0 + 1];
            po0 += acc[nb * 4 + 0] * w0 + acc[nb * 4 + 1] * w1;
            po1 += acc[nb * 4 + 2] * w0 + acc[nb * 4 + 3] * w1;
        }
        po0 += __shfl_xor_sync(0xFFFFFFFFu, po0, 1);
        po0 += __shfl_xor_sync(0xFFFFFFFFu, po0, 2);
        po1 += __shfl_xor_sync(0xFFFFFFFFu, po1, 1);
        po1 += __shfl_xor_sync(0xFFFFFFFFu, po1, 2);
        if (q == 0) {
            if (r0 < B) out[r0] = po0 + bias_out;
            if (r1 < B) out[r1] = po1 + bias_out;
        }
    }
}

extern "C" void kernel_launch(void* const* d_in, const int* in_sizes, int n_in,
                              void* d_out, int out_size)
{
    const float* x    = (const float*)d_in[0];
    const float* W1   = (const float*)d_in[1];
    const float* b1   = (const float*)d_in[2];
    const float* Wh   = (const float*)d_in[3];
    const float* bh   = (const float*)d_in[4];
    const float* Wout = (const float*)d_in[5];
    const float* bout = (const float*)d_in[6];
    float* out = (float*)d_out;

    int B = in_sizes[0] / 6;
    int ntiles = (B + 15) / 16;

    cudaFuncSetAttribute(actuator_hmma_kernel,
                         cudaFuncAttributeMaxDynamicSharedMemorySize, SM_TOTAL);

    int grid = 296;   // persistent: 2 CTAs/SM x 148 SMs
    actuator_hmma_kernel<<<grid, NTHREADS, SM_TOTAL>>>(
        x, W1, b1, Wh, bh, Wout, bout, out, B, ntiles);
}

// round 7
// speedup vs baseline: 1.2800x; 1.2358x over previous
#include <cuda_runtime.h>
#include <cuda_bf16.h>
#include <cstdint>

// ActuatorNet via warp-level mma.sync (HMMA, bf16 hi/lo 3-term split).
// Round 7 = round 4 structure (smem fragment table, __fdividef softsign,
// 256 threads, 2 CTAs/SM) + TWO 16-row tiles per warp: B fragments and bias
// loads are shared across both tiles (fewer issues/row) and the two tiles'
// MMA chains interleave (2x ILP on the tensor pipe's dependency chains).

#define NTHREADS 256
#define NWARPS   8

typedef unsigned long long u64;

// smem layout (bytes)
#define SM_FRAG   0                      // 19*16*32 u64 = 77824
#define SM_W1     77824                  // 192 f32
#define SM_B1     (SM_W1 + 768)          // 32 f32
#define SM_BH     (SM_B1 + 128)          // 19*32 f32 = 2432
#define SM_WOUT   (SM_BH + 2432)         // 32 f32
#define SM_BOUT   (SM_WOUT + 128)        // 1 f32
#define SM_TOTAL  (SM_BOUT + 16)         // ~81.2 KB -> 2 CTAs/SM

__device__ __forceinline__ uint32_t cvt_bf16x2(float hi_elem, float lo_elem) {
    uint32_t r;
    asm("cvt.rn.bf16x2.f32 %0, %1, %2;" : "=r"(r) : "f"(hi_elem), "f"(lo_elem));
    return r;
}

__device__ __forceinline__ void mma_bf16(float* d,
                                         uint32_t a0, uint32_t a1,
                                         uint32_t a2, uint32_t a3,
                                         uint32_t b0, uint32_t b1) {
    asm volatile(
        "mma.sync.aligned.m16n8k16.row.col.f32.bf16.bf16.f32 "
        "{%0,%1,%2,%3}, {%4,%5,%6,%7}, {%8,%9}, {%0,%1,%2,%3};"
        : "+f"(d[0]), "+f"(d[1]), "+f"(d[2]), "+f"(d[3])
        : "r"(a0), "r"(a1), "r"(a2), "r"(a3), "r"(b0), "r"(b1));
}

__device__ __forceinline__ float softsign_f(float v) {
    return __fdividef(v, 1.0f + fabsf(v));
}

// split 16 activations into bf16 hi/lo A fragments
__device__ __forceinline__ void split_frags(const float* acc,
                                            uint32_t* ahi, uint32_t* alo) {
    #pragma unroll
    for (int p = 0; p < 8; p++) {
        float e0 = acc[2 * p], e1 = acc[2 * p + 1];
        uint32_t hp = cvt_bf16x2(e1, e0);
        float f0 = __uint_as_float(hp << 16);
        float f1 = __uint_as_float(hp & 0xFFFF0000u);
        ahi[p] = hp;
        alo[p] = cvt_bf16x2(e1 - f1, e0 - f0);
    }
}

__global__ __launch_bounds__(NTHREADS, 2)
void actuator_hmma_kernel(const float* __restrict__ x,
                          const float* __restrict__ W1,
                          const float* __restrict__ b1,
                          const float* __restrict__ Wh,
                          const float* __restrict__ bh,
                          const float* __restrict__ Wout,
                          const float* __restrict__ bout,
                          float* __restrict__ out,
                          int B, int npairs)
{
    extern __shared__ char smem[];
    u64*   sFRAG = (u64*)(smem + SM_FRAG);
    float* sW1   = (float*)(smem + SM_W1);
    float* sB1   = (float*)(smem + SM_B1);
    float* sBH   = (float*)(smem + SM_BH);
    float* sWOUT = (float*)(smem + SM_WOUT);
    float* sBOUT = (float*)(smem + SM_BOUT);

    const int tid = threadIdx.x;

    // ---- stage small fp32 params ----
    for (int i = tid; i < 192; i += NTHREADS) sW1[i] = W1[i];
    for (int i = tid; i < 32;  i += NTHREADS) sB1[i] = b1[i];
    for (int i = tid; i < 608; i += NTHREADS) sBH[i] = bh[i];
    for (int i = tid; i < 32;  i += NTHREADS) sWOUT[i] = Wout[i];
    if (tid == 0) sBOUT[0] = bout[0];

    // ---- stage hidden weights as per-thread B fragments (hi & lo) ----
    // slot = ((l*16 + combo)*32 + lane), combo = term*8 + ks*4 + nb
    for (int idx = tid; idx < 19 * 16 * 32; idx += NTHREADS) {
        int lane  = idx & 31;
        int combo = (idx >> 5) & 15;
        int l     = idx >> 9;
        int nb    = combo & 3;
        int ks    = (combo >> 2) & 1;
        int term  = combo >> 3;            // 0 = hi, 1 = lo
        int col   = nb * 8 + (lane >> 2);
        int qq    = lane & 3;
        int k0    = ks * 16 + qq * 2;

        const float* Wl = Wh + l * 1024;
        float w0 = Wl[(k0 + 0) * 32 + col];
        float w1 = Wl[(k0 + 1) * 32 + col];
        float w2 = Wl[(k0 + 8) * 32 + col];
        float w3 = Wl[(k0 + 9) * 32 + col];

        uint32_t rb0, rb1;
        if (term == 0) {
            rb0 = cvt_bf16x2(w1, w0);
            rb1 = cvt_bf16x2(w3, w2);
        } else {
            float r0 = w0 - __bfloat162float(__float2bfloat16(w0));
            float r1 = w1 - __bfloat162float(__float2bfloat16(w1));
            float r2 = w2 - __bfloat162float(__float2bfloat16(w2));
            float r3 = w3 - __bfloat162float(__float2bfloat16(w3));
            rb0 = cvt_bf16x2(r1, r0);
            rb1 = cvt_bf16x2(r3, r2);
        }
        sFRAG[idx] = ((u64)rb1 << 32) | rb0;
    }
    __syncthreads();

    const int wid  = tid >> 5;
    const int lane = tid & 31;
    const int g    = lane >> 2;
    const int q    = lane & 3;

    const float bias_out = sBOUT[0];

    for (int pair = blockIdx.x * NWARPS + wid; pair < npairs;
         pair += gridDim.x * NWARPS) {

        int base = pair * 32;
        // tile0 rows: base+g, base+8+g; tile1 rows: base+16+g, base+24+g
        int rA0 = base + g,      rA1 = base + 8 + g;
        int rB0 = base + 16 + g, rB1 = base + 24 + g;
        int cA0 = min(rA0, B - 1), cA1 = min(rA1, B - 1);
        int cB0 = min(rB0, B - 1), cB1 = min(rB1, B - 1);

        float acc0[16], acc1[16];

        // ---- layer 1 (6 -> 32), fp32 SIMT, both tiles ----
        {
            float x0[6], x1[6], x2[6], x3[6];
            const float* p0 = x + (long long)cA0 * 6;
            const float* p1 = x + (long long)cA1 * 6;
            const float* p2 = x + (long long)cB0 * 6;
            const float* p3 = x + (long long)cB1 * 6;
            #pragma unroll
            for (int i = 0; i < 6; i++) {
                x0[i] = __ldg(p0 + i); x1[i] = __ldg(p1 + i);
                x2[i] = __ldg(p2 + i); x3[i] = __ldg(p3 + i);
            }
            #pragma unroll
            for (int nb = 0; nb < 4; nb++) {
                int c0 = nb * 8 + q * 2;
                float b0 = sB1[c0], b1v = sB1[c0 + 1];
                float s00 = b0, s01 = b1v, s10 = b0, s11 = b1v;
                float t00 = b0, t01 = b1v, t10 = b0, t11 = b1v;
                #pragma unroll
                for (int i = 0; i < 6; i++) {
                    float w0 = sW1[i * 32 + c0], w1 = sW1[i * 32 + c0 + 1];
                    s00 += x0[i] * w0; s01 += x0[i] * w1;
                    s10 += x1[i] * w0; s11 += x1[i] * w1;
                    t00 += x2[i] * w0; t01 += x2[i] * w1;
                    t10 += x3[i] * w0; t11 += x3[i] * w1;
                }
                acc0[nb*4+0] = softsign_f(s00); acc0[nb*4+1] = softsign_f(s01);
                acc0[nb*4+2] = softsign_f(s10); acc0[nb*4+3] = softsign_f(s11);
                acc1[nb*4+0] = softsign_f(t00); acc1[nb*4+1] = softsign_f(t01);
                acc1[nb*4+2] = softsign_f(t10); acc1[nb*4+3] = softsign_f(t11);
            }
        }

        // ---- 19 hidden layers via HMMA (two tiles, shared B frags) ----
        for (int l = 0; l < 19; l++) {
            uint32_t ahi0[8], alo0[8], ahi1[8], alo1[8];
            split_frags(acc0, ahi0, alo0);
            split_frags(acc1, ahi1, alo1);

            // re-init accumulators with bias (shared columns)
            const float2* blp = (const float2*)(sBH + l * 32);
            #pragma unroll
            for (int nb = 0; nb < 4; nb++) {
                float2 bb = blp[nb * 4 + q];
                acc0[nb*4+0] = bb.x; acc0[nb*4+1] = bb.y;
                acc0[nb*4+2] = bb.x; acc0[nb*4+3] = bb.y;
                acc1[nb*4+0] = bb.x; acc1[nb*4+1] = bb.y;
                acc1[nb*4+2] = bb.x; acc1[nb*4+3] = bb.y;
            }

            const u64* fl = sFRAG + l * 512 + lane;
            #pragma unroll
            for (int ks = 0; ks < 2; ks++) {
                uint32_t a00 = ahi0[ks*4+0], a01 = ahi0[ks*4+1],
                         a02 = ahi0[ks*4+2], a03 = ahi0[ks*4+3];
                uint32_t l00 = alo0[ks*4+0], l01 = alo0[ks*4+1],
                         l02 = alo0[ks*4+2], l03 = alo0[ks*4+3];
                uint32_t a10 = ahi1[ks*4+0], a11 = ahi1[ks*4+1],
                         a12 = ahi1[ks*4+2], a13 = ahi1[ks*4+3];
                uint32_t l10 = alo1[ks*4+0], l11 = alo1[ks*4+1],
                         l12 = alo1[ks*4+2], l13 = alo1[ks*4+3];
                #pragma unroll
                for (int nb = 0; nb < 4; nb++) {
                    u64 wh = fl[(ks * 4 + nb) * 32];
                    u64 wl = fl[(8 + ks * 4 + nb) * 32];
                    uint32_t bh0 = (uint32_t)wh, bh1 = (uint32_t)(wh >> 32);
                    uint32_t bl0 = (uint32_t)wl, bl1 = (uint32_t)(wl >> 32);
                    float* d0 = acc0 + nb * 4;
                    float* d1 = acc1 + nb * 4;
                    mma_bf16(d0, a00, a01, a02, a03, bh0, bh1);  // t0 hi*Whi
                    mma_bf16(d1, a10, a11, a12, a13, bh0, bh1);  // t1 hi*Whi
                    mma_bf16(d0, l00, l01, l02, l03, bh0, bh1);  // t0 lo*Whi
                    mma_bf16(d1, l10, l11, l12, l13, bh0, bh1);  // t1 lo*Whi
                    mma_bf16(d0, a00, a01, a02, a03, bl0, bl1);  // t0 hi*Wlo
                    mma_bf16(d1, a10, a11, a12, a13, bl0, bl1);  // t1 hi*Wlo
                }
            }

            #pragma unroll
            for (int i = 0; i < 16; i++) {
                acc0[i] = softsign_f(acc0[i]);
                acc1[i] = softsign_f(acc1[i]);
            }
        }

        // ---- output layer (32 -> 1) + quad reduction, both tiles ----
        float pA0 = 0.0f, pA1 = 0.0f, pB0 = 0.0f, pB1 = 0.0f;
        #pragma unroll
        for (int nb = 0; nb < 4; nb++) {
            int c0 = nb * 8 + q * 2;
            float w0 = sWOUT[c0], w1 = sWOUT[c0 + 1];
            pA0 += acc0[nb*4+0] * w0 + acc0[nb*4+1] * w1;
            pA1 += acc0[nb*4+2] * w0 + acc0[nb*4+3] * w1;
            pB0 += acc1[nb*4+0] * w0 + acc1[nb*4+1] * w1;
            pB1 += acc1[nb*4+2] * w0 + acc1[nb*4+3] * w1;
        }
        pA0 += __shfl_xor_sync(0xFFFFFFFFu, pA0, 1);
        pA0 += __shfl_xor_sync(0xFFFFFFFFu, pA0, 2);
        pA1 += __shfl_xor_sync(0xFFFFFFFFu, pA1, 1);
        pA1 += __shfl_xor_sync(0xFFFFFFFFu, pA1, 2);
        pB0 += __shfl_xor_sync(0xFFFFFFFFu, pB0, 1);
        pB0 += __shfl_xor_sync(0xFFFFFFFFu, pB0, 2);
        pB1 += __shfl_xor_sync(0xFFFFFFFFu, pB1, 1);
        pB1 += __shfl_xor_sync(0xFFFFFFFFu, pB1, 2);
        if (q == 0) {
            if (rA0 < B) out[rA0] = pA0 + bias_out;
            if (rA1 < B) out[rA1] = pA1 + bias_out;
            if (rB0 < B) out[rB0] = pB0 + bias_out;
            if (rB1 < B) out[rB1] = pB1 + bias_out;
        }
    }
}

extern "C" void kernel_launch(void* const* d_in, const int* in_sizes, int n_in,
                              void* d_out, int out_size)
{
    const float* x    = (const float*)d_in[0];
    const float* W1   = (const float*)d_in[1];
    const float* b1   = (const float*)d_in[2];
    const float* Wh   = (const float*)d_in[3];
    const float* bh   = (const float*)d_in[4];
    const float* Wout = (const float*)d_in[5];
    const float* bout = (const float*)d_in[6];
    float* out = (float*)d_out;

    int B = in_sizes[0] / 6;
    int npairs = (B + 31) / 32;

    cudaFuncSetAttribute(actuator_hmma_kernel,
                         cudaFuncAttributeMaxDynamicSharedMemorySize, SM_TOTAL);

    int grid = 296;   // persistent: 2 CTAs/SM x 148 SMs
    actuator_hmma_kernel<<<grid, NTHREADS, SM_TOTAL>>>(
        x, W1, b1, Wh, bh, Wout, bout, out, B, npairs);
}